// round 6
// baseline (speedup 1.0000x reference)
#include <cuda_runtime.h>
#include <cuda_bf16.h>
#include <math.h>

// Problem constants
#define QS 256
#define LS 2048
#define NB 64
#define SS 26
#define NPOST (NB * LS * QS)     // 33,554,432
#define EM_ROWS 64

// fb geometry: 512 threads = 16 warps
//   warp: wcol = wid&7 (32-column block), h = wid>>3 (row half)
//   lane: g = lane>>3 (row group within half), li = lane&7 (4-column slot)
//   thread -> columns cc..cc+3 (cc = 32*wcol + 4*li), rows r0..r0+31 (r0 = 128h+32g)
//   rows r0..r0+19  : fp32 packed regs (40 u64 = 80 regs)
//   rows r0+20..+31 : bf16 pairs in shared (24 u32, pitch 28)
#define MYROW_PITCH 28
#define MYROW_U32 (512 * MYROW_PITCH)          // 14336
#define PD_U32 544                              // duplicated p: 2*256 + 4*8 pad
#define COMB_U32 512                            // 2 halves * 8 wcol * 8 li * 4
#define RED_U32 16

// ---------------------------------------------------------------------------
// Device scratch
// ---------------------------------------------------------------------------
__device__ float g_expA[QS * QS];     // exp(log_A)  [j][i]
__device__ float g_expAT[QS * QS];    // transpose
__device__ float g_expB[QS * 32];
__device__ float g_pi[QS];
__device__ float g_emit[NPOST];       // [b][l][q]
__device__ float g_alpha[NPOST];
__device__ float g_beta[NPOST];
__device__ float g_Ca[NB * LS];
__device__ float g_Cb[NB * LS];
__device__ float g_loglik[NB];

// ---------------------------------------------------------------------------
// f32x2 helpers
// ---------------------------------------------------------------------------
__device__ __forceinline__ unsigned long long pk(float x, float y) {
    unsigned long long r;
    asm("mov.b64 %0, {%1,%2};" : "=l"(r) : "f"(x), "f"(y));
    return r;
}
__device__ __forceinline__ void ffma2(unsigned long long& c,
                                      unsigned long long a,
                                      unsigned long long b) {
    asm("fma.rn.f32x2 %0, %1, %2, %0;" : "+l"(c) : "l"(a), "l"(b));
}
__device__ __forceinline__ unsigned long long mul2(unsigned long long a,
                                                   unsigned long long b) {
    unsigned long long r;
    asm("mul.rn.f32x2 %0, %1, %2;" : "=l"(r) : "l"(a), "l"(b));
    return r;
}
__device__ __forceinline__ unsigned long long add2(unsigned long long a,
                                                   unsigned long long b) {
    unsigned long long r;
    asm("add.rn.f32x2 %0, %1, %2;" : "=l"(r) : "l"(a), "l"(b));
    return r;
}
__device__ __forceinline__ float2 unpk(unsigned long long u) {
    float lo, hi;
    asm("mov.b64 {%0,%1}, %2;" : "=f"(lo), "=f"(hi) : "l"(u));
    return make_float2(lo, hi);
}
__device__ __forceinline__ unsigned long long bf2f(unsigned int w) {
    unsigned int lo = w << 16;
    unsigned int hi = w & 0xffff0000u;
    unsigned long long r;
    asm("mov.b64 %0, {%1,%2};" : "=l"(r) : "r"(lo), "r"(hi));
    return r;
}
__device__ __forceinline__ unsigned int pack_bf16(float a, float b) {
    __nv_bfloat16 b0 = __float2bfloat16(a);
    __nv_bfloat16 b1 = __float2bfloat16(b);
    return (unsigned int)__bfloat16_as_ushort(b0) |
           ((unsigned int)__bfloat16_as_ushort(b1) << 16);
}

// ---------------------------------------------------------------------------
// Kernel 0: exp() of parameters
// ---------------------------------------------------------------------------
__global__ void precompute_kernel(const float* __restrict__ log_A,
                                  const float* __restrict__ log_pi,
                                  const float* __restrict__ log_B) {
    int idx = blockIdx.x * 256 + threadIdx.x;
    if (blockIdx.x < 256) {
        float v = expf(log_A[idx]);
        g_expA[idx] = v;
        int j = idx >> 8, i = idx & 255;
        g_expAT[i * QS + j] = v;
    } else if (blockIdx.x < 282) {
        int k = idx - 65536;
        if (k < QS * SS) {
            int q = k / SS, s = k - q * SS;
            g_expB[q * 32 + s] = expf(log_B[k]);
        }
    } else {
        if (threadIdx.x < QS) g_pi[threadIdx.x] = expf(log_pi[threadIdx.x]);
    }
}

// ---------------------------------------------------------------------------
// Kernel 1: emission GEMM
// ---------------------------------------------------------------------------
__global__ void __launch_bounds__(256) emission_kernel(const float* __restrict__ inputs) {
    __shared__ float in_sh[EM_ROWS][SS];
    int tid = threadIdx.x;
    int row0 = blockIdx.x * EM_ROWS;

    for (int i = tid; i < EM_ROWS * SS; i += 256)
        in_sh[i / SS][i % SS] = inputs[row0 * SS + i];
    float eb[SS];
#pragma unroll
    for (int s = 0; s < SS; s++) eb[s] = g_expB[tid * 32 + s];
    __syncthreads();

#pragma unroll 4
    for (int r = 0; r < EM_ROWS; r++) {
        float acc = 0.0f;
#pragma unroll
        for (int s = 0; s < SS; s++) acc = fmaf(in_sh[r][s], eb[s], acc);
        g_emit[(size_t)(row0 + r) * QS + tid] = acc;
    }
}

// ---------------------------------------------------------------------------
// Kernel 2: scaled forward/backward, 512 threads, deferred renormalization.
// Block 0..63 forward chain b; block 64..127 backward chain b-64.
// ---------------------------------------------------------------------------
extern __shared__ unsigned int shu[];

#define SH_MYROW  (shu)
#define SH_PD(bf) ((float*)(shu + MYROW_U32 + (bf) * PD_U32))
#define SH_COMB   ((float*)(shu + MYROW_U32 + 2 * PD_U32))
#define SH_RED    ((float*)(shu + MYROW_U32 + 2 * PD_U32 + COMB_U32))

__global__ void __launch_bounds__(512, 1) fb_kernel() {
    int tid  = threadIdx.x;
    int wid  = tid >> 5;
    int lane = tid & 31;
    int wcol = wid & 7;
    int h    = wid >> 3;
    int g    = lane >> 3;
    int li   = lane & 7;
    int cc   = wcol * 32 + 4 * li;       // my 4 columns cc..cc+3
    int r0   = 128 * h + 32 * g;         // my 32 rows r0..r0+31

    int bx = blockIdx.x;
    bool fwd = (bx < NB);
    int b = fwd ? bx : bx - NB;
    const float* Ag = fwd ? g_expA : g_expAT;

    // rows r0..r0+19 -> fp32 column-pair registers: Areg[2j]=(cc,cc+1) Areg[2j+1]=(cc+2,cc+3)
    unsigned long long Areg[40];
#pragma unroll
    for (int j = 0; j < 20; j++) {
        const float* row = Ag + (r0 + j) * QS + cc;
        Areg[2 * j]     = pk(row[0], row[1]);
        Areg[2 * j + 1] = pk(row[2], row[3]);
    }
    // rows r0+20..r0+31 -> bf16 column-pairs in private shared row
    unsigned int* myrow = SH_MYROW + tid * MYROW_PITCH;
#pragma unroll
    for (int n = 0; n < 12; n++) {
        const float* row = Ag + (r0 + 20 + n) * QS + cc;
        myrow[2 * n]     = pack_bf16(row[0], row[1]);
        myrow[2 * n + 1] = pack_bf16(row[2], row[3]);
    }
    const uint4* m4 = (const uint4*)myrow;

    const float* em_b = g_emit + (size_t)b * LS * QS;
    float* st_b = (fwd ? g_alpha : g_beta) + (size_t)b * LS * QS;
    float* C_b  = (fwd ? g_Ca : g_Cb) + b * LS;

    // duplicated-p group base (u32 units): group (4h+g) starts at 68*(4h+g)
    int pd_base = 68 * (4 * h + g);
    int combW = ((h * 8 + wcol) * 8 + li) * 4;
    int combR = (((h ^ 1) * 8 + wcol) * 8 + li) * 4;
    bool writer = (h == 0) && (g == 0);

    // --- init t boundary state ---
    if (tid < QS) {
        int s = tid;
        int slot = 2 * s + 4 * (s >> 5);
        if (fwd) {
            float v = g_pi[s] * em_b[s];
            st_b[s] = v;
            SH_PD(0)[slot] = v; SH_PD(0)[slot + 1] = v;
            if (s == 0) C_b[0] = 0.0f;
        } else {
            st_b[(size_t)(LS - 1) * QS + s] = 1.0f;
            float e = em_b[(size_t)(LS - 1) * QS + s];
            SH_PD(0)[slot] = e; SH_PD(0)[slot + 1] = e;
            if (s == 0) C_b[LS - 1] = 0.0f;
        }
    }
    __syncthreads();

    double C = 0.0;
    int cur = 0;
    int t    = fwd ? 1 : (LS - 2);
    int tend = fwd ? LS : -1;
    int tinc = fwd ? 1 : -1;

    for (; t != tend; t += tinc) {
        float4 e4 = *(const float4*)(em_b + (size_t)t * QS + cc);   // LDG, hidden by matvec

        // ---- matvec over my 32 rows x 4 cols ----
        const ulonglong2* pdv = (const ulonglong2*)(SH_PD(cur) + pd_base);
        unsigned long long acc0, acc1;
        {
            ulonglong2 q = pdv[0];
            acc0 = mul2(Areg[0], q.x);
            acc1 = mul2(Areg[1], q.x);
            ffma2(acc0, Areg[2], q.y);
            ffma2(acc1, Areg[3], q.y);
        }
#pragma unroll
        for (int k = 1; k < 10; k++) {
            ulonglong2 q = pdv[k];
            ffma2(acc0, Areg[4 * k],     q.x);
            ffma2(acc1, Areg[4 * k + 1], q.x);
            ffma2(acc0, Areg[4 * k + 2], q.y);
            ffma2(acc1, Areg[4 * k + 3], q.y);
        }
#pragma unroll
        for (int m = 0; m < 6; m++) {
            uint4 w = m4[m];
            ulonglong2 q = pdv[10 + m];
            ffma2(acc0, bf2f(w.x), q.x);
            ffma2(acc1, bf2f(w.y), q.x);
            ffma2(acc0, bf2f(w.z), q.y);
            ffma2(acc1, bf2f(w.w), q.y);
        }

        // ---- reduce across the 4 row-groups (symmetric, SEL-free) ----
        const unsigned FULL = 0xffffffffu;
        acc0 = add2(acc0, __shfl_xor_sync(FULL, acc0, 8));
        acc1 = add2(acc1, __shfl_xor_sync(FULL, acc1, 8));
        acc0 = add2(acc0, __shfl_xor_sync(FULL, acc0, 16));
        acc1 = add2(acc1, __shfl_xor_sync(FULL, acc1, 16));

        // ---- exchange halves via shared ----
        if (g == 0)
            *(ulonglong2*)(SH_COMB + combW) = make_ulonglong2(acc0, acc1);
        __syncthreads();
        {
            ulonglong2 oth = *(const ulonglong2*)(SH_COMB + combR);
            acc0 = add2(acc0, oth.x);
            acc1 = add2(acc1, oth.y);
        }

        float Ct = (float)C;
        bool renorm = fwd ? ((t & 15) == 15) : ((t & 15) == 0);

        if (fwd) {
            // v2 = mv * e  (stored value, pre-norm)
            acc0 = mul2(acc0, pk(e4.x, e4.y));
            acc1 = mul2(acc1, pk(e4.z, e4.w));
            float2 f0 = unpk(acc0), f1 = unpk(acc1);
            float4 stv = make_float4(f0.x, f0.y, f1.x, f1.y);

            if (renorm) {
                float ls = (f0.x + f0.y) + (f1.x + f1.y);
#pragma unroll
                for (int o = 16; o > 0; o >>= 1) ls += __shfl_xor_sync(FULL, ls, o);
                if (lane == 0) SH_RED[wid] = ls;
                __syncthreads();
                float s = 0.0f;
#pragma unroll
                for (int w = 0; w < 16; w++) s += SH_RED[w];
                s *= 0.125f;
                if (t == LS - 1 && tid == 0)
                    g_loglik[b] = (float)(C + (double)logf(s));
                C += (double)logf(s);
                float inv = 1.0f / s;
                unsigned long long iv = pk(inv, inv);
                acc0 = mul2(acc0, iv);
                acc1 = mul2(acc1, iv);
            }
            if (writer) {
                *(float4*)(st_b + (size_t)t * QS + cc) = stv;
                float2 p0 = unpk(acc0), p1 = unpk(acc1);
                int base = 2 * cc + 4 * (cc >> 5);
                *(ulonglong2*)(SH_PD(cur ^ 1) + base) =
                    make_ulonglong2(pk(p0.x, p0.x), pk(p0.y, p0.y));
                *(ulonglong2*)(SH_PD(cur ^ 1) + base + 4) =
                    make_ulonglong2(pk(p1.x, p1.x), pk(p1.y, p1.y));
                if (tid == 0) C_b[t] = Ct;
            }
        } else {
            float2 f0 = unpk(acc0), f1 = unpk(acc1);
            float4 stv = make_float4(f0.x, f0.y, f1.x, f1.y);

            if (renorm) {
                float ls = (f0.x + f0.y) + (f1.x + f1.y);
#pragma unroll
                for (int o = 16; o > 0; o >>= 1) ls += __shfl_xor_sync(FULL, ls, o);
                if (lane == 0) SH_RED[wid] = ls;
                __syncthreads();
                float s = 0.0f;
#pragma unroll
                for (int w = 0; w < 16; w++) s += SH_RED[w];
                s *= 0.125f;
                C += (double)logf(s);
                float inv = 1.0f / s;
                unsigned long long iv = pk(inv, inv);
                acc0 = mul2(acc0, iv);
                acc1 = mul2(acc1, iv);
            }
            // p_next = e_t * q_t
            acc0 = mul2(acc0, pk(e4.x, e4.y));
            acc1 = mul2(acc1, pk(e4.z, e4.w));
            if (writer) {
                *(float4*)(st_b + (size_t)t * QS + cc) = stv;
                float2 p0 = unpk(acc0), p1 = unpk(acc1);
                int base = 2 * cc + 4 * (cc >> 5);
                *(ulonglong2*)(SH_PD(cur ^ 1) + base) =
                    make_ulonglong2(pk(p0.x, p0.x), pk(p0.y, p0.y));
                *(ulonglong2*)(SH_PD(cur ^ 1) + base + 4) =
                    make_ulonglong2(pk(p1.x, p1.x), pk(p1.y, p1.y));
                if (tid == 0) C_b[t] = Ct;
            }
        }
        __syncthreads();
        cur ^= 1;
    }
}

// ---------------------------------------------------------------------------
// Kernel 3: posterior + loglik
// ---------------------------------------------------------------------------
__global__ void __launch_bounds__(256) posterior_kernel(float* __restrict__ out, int out_size) {
    int i4 = blockIdx.x * 256 + threadIdx.x;
    int idx = i4 << 2;
    int bt = idx >> 8;
    int b  = bt >> 11;
    float4 a  = *(const float4*)(g_alpha + idx);
    float4 be = *(const float4*)(g_beta + idx);
    float c = g_Ca[bt] + g_Cb[bt] - g_loglik[b];
    float4 o;
    o.x = logf(a.x * be.x) + c;
    o.y = logf(a.y * be.y) + c;
    o.z = logf(a.z * be.z) + c;
    o.w = logf(a.w * be.w) + c;
    *(float4*)(out + idx) = o;
    if (i4 < NB && out_size >= NPOST + NB)
        out[NPOST + i4] = g_loglik[i4];
}

// ---------------------------------------------------------------------------
// Launch
// ---------------------------------------------------------------------------
extern "C" void kernel_launch(void* const* d_in, const int* in_sizes, int n_in,
                              void* d_out, int out_size) {
    const float* inputs = (const float*)d_in[0];   // (1,64,2048,26)
    const float* log_A  = (const float*)d_in[1];   // (1,256,256)
    const float* log_pi = (const float*)d_in[2];   // (1,256)
    const float* log_B  = (const float*)d_in[3];   // (1,256,26)
    float* out = (float*)d_out;

    precompute_kernel<<<283, 256>>>(log_A, log_pi, log_B);
    emission_kernel<<<(NB * LS) / EM_ROWS, 256>>>(inputs);

    int smem = (MYROW_U32 + 2 * PD_U32 + COMB_U32 + RED_U32) * (int)sizeof(unsigned int);
    cudaFuncSetAttribute(fb_kernel, cudaFuncAttributeMaxDynamicSharedMemorySize, smem);
    fb_kernel<<<2 * NB, 512, smem>>>();

    posterior_kernel<<<NPOST / 1024, 256>>>(out, out_size);
}

// round 8
// speedup vs baseline: 1.0574x; 1.0574x over previous
#include <cuda_runtime.h>
#include <cuda_bf16.h>
#include <math.h>

// Problem constants
#define QS 256
#define LS 2048
#define NB 64
#define SS 26
#define NPOST (NB * LS * QS)     // 33,554,432
#define EM_ROWS 64

// fb geometry: 256 threads = 8 warps
//   warp w owns columns [32w, 32w+32)
//   lane: g = lane>>3 (row group), li = lane&7; cc = 32w + 4*li; rows [64g, 64g+64)
//   rows r0..r0+39  : fp32 row-pair regs   (20 pairs x 4 cols = 80 u64 = 160 regs)
//   rows r0+40..+63 : fp32 row-pairs in shared (12 pairs x 4 cols = 48 u64 = 96 u32)
#define MYROW_PITCH 100          // 96 payload u32 + 4 pad -> conflict-free LDS.128
#define MYROW_U32 (256 * MYROW_PITCH)    // 25600 u32 = 100 KB

// ---------------------------------------------------------------------------
// Device scratch
// ---------------------------------------------------------------------------
__device__ float g_expA[QS * QS];     // exp(log_A)  [j][i]
__device__ float g_expAT[QS * QS];    // transpose
__device__ float g_expB[QS * 32];
__device__ float g_pi[QS];
__device__ float g_emit[NPOST];       // [b][l][q]
__device__ float g_alpha[NPOST];
__device__ float g_beta[NPOST];
__device__ float g_Ca[NB * LS];
__device__ float g_Cb[NB * LS];
__device__ float g_loglik[NB];

// ---------------------------------------------------------------------------
// f32x2 helpers
// ---------------------------------------------------------------------------
__device__ __forceinline__ unsigned long long pk(float x, float y) {
    unsigned long long r;
    asm("mov.b64 %0, {%1,%2};" : "=l"(r) : "f"(x), "f"(y));
    return r;
}
__device__ __forceinline__ void ffma2(unsigned long long& c,
                                      unsigned long long a,
                                      unsigned long long b) {
    asm("fma.rn.f32x2 %0, %1, %2, %0;" : "+l"(c) : "l"(a), "l"(b));
}
__device__ __forceinline__ unsigned long long mul2(unsigned long long a,
                                                   unsigned long long b) {
    unsigned long long r;
    asm("mul.rn.f32x2 %0, %1, %2;" : "=l"(r) : "l"(a), "l"(b));
    return r;
}
__device__ __forceinline__ unsigned long long add2(unsigned long long a,
                                                   unsigned long long b) {
    unsigned long long r;
    asm("add.rn.f32x2 %0, %1, %2;" : "=l"(r) : "l"(a), "l"(b));
    return r;
}
__device__ __forceinline__ float2 unpk(unsigned long long u) {
    float lo, hi;
    asm("mov.b64 {%0,%1}, %2;" : "=f"(lo), "=f"(hi) : "l"(u));
    return make_float2(lo, hi);
}
__device__ __forceinline__ unsigned long long shfl_xor_u64(unsigned long long v, int m) {
    float2 f = unpk(v);
    f.x = __shfl_xor_sync(0xffffffffu, f.x, m);
    f.y = __shfl_xor_sync(0xffffffffu, f.y, m);
    return pk(f.x, f.y);
}

// ---------------------------------------------------------------------------
// Kernel 0: exp() of parameters
// ---------------------------------------------------------------------------
__global__ void precompute_kernel(const float* __restrict__ log_A,
                                  const float* __restrict__ log_pi,
                                  const float* __restrict__ log_B) {
    int idx = blockIdx.x * 256 + threadIdx.x;
    if (blockIdx.x < 256) {
        float v = expf(log_A[idx]);
        g_expA[idx] = v;
        int j = idx >> 8, i = idx & 255;
        g_expAT[i * QS + j] = v;
    } else if (blockIdx.x < 282) {
        int k = idx - 65536;
        if (k < QS * SS) {
            int q = k / SS, s = k - q * SS;
            g_expB[q * 32 + s] = expf(log_B[k]);
        }
    } else {
        if (threadIdx.x < QS) g_pi[threadIdx.x] = expf(log_pi[threadIdx.x]);
    }
}

// ---------------------------------------------------------------------------
// Kernel 1: emission GEMM
// ---------------------------------------------------------------------------
__global__ void __launch_bounds__(256) emission_kernel(const float* __restrict__ inputs) {
    __shared__ float in_sh[EM_ROWS][SS];
    int tid = threadIdx.x;
    int row0 = blockIdx.x * EM_ROWS;

    for (int i = tid; i < EM_ROWS * SS; i += 256)
        in_sh[i / SS][i % SS] = inputs[row0 * SS + i];
    float eb[SS];
#pragma unroll
    for (int s = 0; s < SS; s++) eb[s] = g_expB[tid * 32 + s];
    __syncthreads();

#pragma unroll 4
    for (int r = 0; r < EM_ROWS; r++) {
        float acc = 0.0f;
#pragma unroll
        for (int s = 0; s < SS; s++) acc = fmaf(in_sh[r][s], eb[s], acc);
        g_emit[(size_t)(row0 + r) * QS + tid] = acc;
    }
}

// ---------------------------------------------------------------------------
// ncu alignment marker (no work; shifts fb to the profiled launch slot)
// ---------------------------------------------------------------------------
__global__ void fb_marker_kernel() {}

// ---------------------------------------------------------------------------
// Kernel 2: scaled forward/backward, deferred renormalization, pure fp32.
// Block 0..63 forward chain b; block 64..127 backward chain b-64.
// ---------------------------------------------------------------------------
extern __shared__ unsigned int shu[];

#define SH_MYROW  (shu)
#define SH_P(bf)  ((float*)(shu + MYROW_U32 + (bf) * QS))
#define SH_RED    ((float*)(shu + MYROW_U32 + 2 * QS))

__global__ void __launch_bounds__(256, 1) fb_kernel() {
    int tid  = threadIdx.x;
    int w    = tid >> 5;
    int lane = tid & 31;
    int g    = lane >> 3;
    int li   = lane & 7;
    int cc   = 32 * w + 4 * li;          // my 4 columns
    int r0   = 64 * g;                   // my 64 rows

    int bx = blockIdx.x;
    bool fwd = (bx < NB);
    int b = fwd ? bx : bx - NB;
    const float* Ag = fwd ? g_expA : g_expAT;

    // rows r0..r0+39 -> fp32 row-pair regs: Areg[j2*4+c] = (A[r0+2j2][cc+c], A[r0+2j2+1][cc+c])
    unsigned long long Areg[80];
#pragma unroll
    for (int j2 = 0; j2 < 20; j2++) {
        const float* ra = Ag + (r0 + 2 * j2) * QS + cc;
        const float* rb = ra + QS;
#pragma unroll
        for (int c = 0; c < 4; c++)
            Areg[j2 * 4 + c] = pk(ra[c], rb[c]);
    }
    // rows r0+40..r0+63 -> fp32 row-pairs in private shared row
    unsigned long long* myrow64 =
        (unsigned long long*)(SH_MYROW + tid * MYROW_PITCH);
#pragma unroll
    for (int j2 = 0; j2 < 12; j2++) {
        const float* ra = Ag + (r0 + 40 + 2 * j2) * QS + cc;
        const float* rb = ra + QS;
#pragma unroll
        for (int c = 0; c < 4; c++)
            myrow64[j2 * 4 + c] = pk(ra[c], rb[c]);
    }

    const float* em_b = g_emit + (size_t)b * LS * QS;
    float* st_b = (fwd ? g_alpha : g_beta) + (size_t)b * LS * QS;
    float* C_b  = (fwd ? g_Ca : g_Cb) + b * LS;

    // --- boundary init ---
    {
        int s = tid;
        if (fwd) {
            float v = g_pi[s] * em_b[s];
            st_b[s] = v;
            SH_P(0)[s] = v;
            if (s == 0) C_b[0] = 0.0f;
        } else {
            st_b[(size_t)(LS - 1) * QS + s] = 1.0f;
            SH_P(0)[s] = em_b[(size_t)(LS - 1) * QS + s];
            if (s == 0) C_b[LS - 1] = 0.0f;
        }
    }
    __syncthreads();

    double C = 0.0;
    int cur = 0;
    int t    = fwd ? 1 : (LS - 2);
    int tend = fwd ? LS : -1;
    int tinc = fwd ? 1 : -1;
    const unsigned FULL = 0xffffffffu;

    for (; t != tend; t += tinc) {
        float4 e4 = *(const float4*)(em_b + (size_t)t * QS + cc);

        // ---- matvec: my 64 rows x 4 cols ----
        const ulonglong2* pdv = (const ulonglong2*)(SH_P(cur) + r0);
        unsigned long long acc[4];
        {
            ulonglong2 q = pdv[0];                 // (p[r0],p[r0+1]) , (p[r0+2],p[r0+3])
            acc[0] = mul2(Areg[0], q.x);
            acc[1] = mul2(Areg[1], q.x);
            acc[2] = mul2(Areg[2], q.x);
            acc[3] = mul2(Areg[3], q.x);
            ffma2(acc[0], Areg[4], q.y);
            ffma2(acc[1], Areg[5], q.y);
            ffma2(acc[2], Areg[6], q.y);
            ffma2(acc[3], Areg[7], q.y);
        }
#pragma unroll
        for (int k = 1; k < 10; k++) {
            ulonglong2 q = pdv[k];
#pragma unroll
            for (int c = 0; c < 4; c++) ffma2(acc[c], Areg[8 * k + c], q.x);
#pragma unroll
            for (int c = 0; c < 4; c++) ffma2(acc[c], Areg[8 * k + 4 + c], q.y);
        }
        // shared fp32 rows: pairs (2k, 2k+1), 4 LDS.128 per k
#pragma unroll
        for (int k = 0; k < 6; k++) {
            ulonglong2 q = pdv[10 + k];
            const ulonglong2* mrow = (const ulonglong2*)(myrow64 + 8 * k);
            ulonglong2 wa0 = mrow[0];   // pair 2k,   cols 0,1
            ulonglong2 wa1 = mrow[1];   // pair 2k,   cols 2,3
            ulonglong2 wb0 = mrow[2];   // pair 2k+1, cols 0,1
            ulonglong2 wb1 = mrow[3];   // pair 2k+1, cols 2,3
            ffma2(acc[0], wa0.x, q.x);
            ffma2(acc[1], wa0.y, q.x);
            ffma2(acc[2], wa1.x, q.x);
            ffma2(acc[3], wa1.y, q.x);
            ffma2(acc[0], wb0.x, q.y);
            ffma2(acc[1], wb0.y, q.y);
            ffma2(acc[2], wb1.x, q.y);
            ffma2(acc[3], wb1.y, q.y);
        }

        // ---- reduce across the 4 row-groups (symmetric butterfly) ----
#pragma unroll
        for (int c = 0; c < 4; c++) acc[c] = add2(acc[c], shfl_xor_u64(acc[c], 8));
#pragma unroll
        for (int c = 0; c < 4; c++) acc[c] = add2(acc[c], shfl_xor_u64(acc[c], 16));

        float2 s0 = unpk(acc[0]), s1 = unpk(acc[1]), s2 = unpk(acc[2]), s3 = unpk(acc[3]);
        float m0 = s0.x + s0.y, m1 = s1.x + s1.y, m2 = s2.x + s2.y, m3 = s3.x + s3.y;

        float Ct = (float)C;
        bool renorm = fwd ? ((t & 15) == 15) : ((t & 15) == 0);
        float4 stv;
        float4 pv;

        if (fwd) {
            stv = make_float4(m0 * e4.x, m1 * e4.y, m2 * e4.z, m3 * e4.w);
            pv = stv;
            if (renorm) {
                float ls = (stv.x + stv.y) + (stv.z + stv.w);
                ls += __shfl_xor_sync(FULL, ls, 1);
                ls += __shfl_xor_sync(FULL, ls, 2);
                ls += __shfl_xor_sync(FULL, ls, 4);
                if (lane == 0) SH_RED[w] = ls;
                __syncthreads();
                float s = 0.0f;
#pragma unroll
                for (int ww = 0; ww < 8; ww++) s += SH_RED[ww];
                if (t == LS - 1 && tid == 0)
                    g_loglik[b] = (float)(C + (double)logf(s));
                C += (double)logf(s);
                float inv = 1.0f / s;
                pv = make_float4(stv.x * inv, stv.y * inv, stv.z * inv, stv.w * inv);
            }
        } else {
            stv = make_float4(m0, m1, m2, m3);
            float4 q = stv;
            if (renorm) {
                float ls = (m0 + m1) + (m2 + m3);
                ls += __shfl_xor_sync(FULL, ls, 1);
                ls += __shfl_xor_sync(FULL, ls, 2);
                ls += __shfl_xor_sync(FULL, ls, 4);
                if (lane == 0) SH_RED[w] = ls;
                __syncthreads();
                float s = 0.0f;
#pragma unroll
                for (int ww = 0; ww < 8; ww++) s += SH_RED[ww];
                C += (double)logf(s);
                float inv = 1.0f / s;
                q = make_float4(m0 * inv, m1 * inv, m2 * inv, m3 * inv);
            }
            pv = make_float4(q.x * e4.x, q.y * e4.y, q.z * e4.z, q.w * e4.w);
        }

        if (g == 0)
            *(float4*)(SH_P(cur ^ 1) + cc) = pv;
        __syncthreads();
        if (g == 0)
            *(float4*)(st_b + (size_t)t * QS + cc) = stv;   // overlaps next matvec
        if (tid == 0) C_b[t] = Ct;
        cur ^= 1;
    }
}

// ---------------------------------------------------------------------------
// Kernel 3: posterior + loglik
// ---------------------------------------------------------------------------
__global__ void __launch_bounds__(256) posterior_kernel(float* __restrict__ out, int out_size) {
    int i4 = blockIdx.x * 256 + threadIdx.x;
    int idx = i4 << 2;
    int bt = idx >> 8;
    int b  = bt >> 11;
    float4 a  = *(const float4*)(g_alpha + idx);
    float4 be = *(const float4*)(g_beta + idx);
    float c = g_Ca[bt] + g_Cb[bt] - g_loglik[b];
    float4 o;
    o.x = logf(a.x * be.x) + c;
    o.y = logf(a.y * be.y) + c;
    o.z = logf(a.z * be.z) + c;
    o.w = logf(a.w * be.w) + c;
    *(float4*)(out + idx) = o;
    if (i4 < NB && out_size >= NPOST + NB)
        out[NPOST + i4] = g_loglik[i4];
}

// ---------------------------------------------------------------------------
// Launch
// ---------------------------------------------------------------------------
extern "C" void kernel_launch(void* const* d_in, const int* in_sizes, int n_in,
                              void* d_out, int out_size) {
    const float* inputs = (const float*)d_in[0];   // (1,64,2048,26)
    const float* log_A  = (const float*)d_in[1];   // (1,256,256)
    const float* log_pi = (const float*)d_in[2];   // (1,256)
    const float* log_B  = (const float*)d_in[3];   // (1,256,26)
    float* out = (float*)d_out;

    precompute_kernel<<<283, 256>>>(log_A, log_pi, log_B);
    emission_kernel<<<(NB * LS) / EM_ROWS, 256>>>(inputs);
    fb_marker_kernel<<<1, 32>>>();                 // shifts fb into ncu's -s 5 slot

    int smem = (MYROW_U32 + 2 * QS + 16) * (int)sizeof(unsigned int);
    cudaFuncSetAttribute(fb_kernel, cudaFuncAttributeMaxDynamicSharedMemorySize, smem);
    fb_kernel<<<2 * NB, 256, smem>>>();

    posterior_kernel<<<NPOST / 1024, 256>>>(out, out_size);
}

// round 9
// speedup vs baseline: 1.1669x; 1.1035x over previous
#include <cuda_runtime.h>
#include <cuda_bf16.h>
#include <math.h>

// Problem constants
#define QS 256
#define LS 2048
#define NB 64
#define SS 26
#define NPOST (NB * LS * QS)     // 33,554,432
#define EM_ROWS 64

// fb geometry: 256 threads = 8 warps
//   warp w owns columns [32w, 32w+32)
//   lane: g = lane>>3 (row group), li = lane&7; cc = 32w + 4*li; rows [64g, 64g+64)
//   rows r0..r0+39  : fp32 row-pair regs   (20 pairs x 4 cols = 80 u64 = 160 regs)
//   rows r0+40..+63 : fp32 row-pairs in shared (12 pairs x 4 cols = 48 u64 = 96 u32)
#define MYROW_PITCH 100          // 96 payload u32 + 4 pad
#define MYROW_U32 (256 * MYROW_PITCH)    // 25600 u32 = 100 KB

// Skewed p buffer: 4 chunks of 64 floats, 16B pad between chunks.
// Group g's chunk starts at 68g floats = 272g bytes -> banks shift by 4 per
// group -> the 4 row-groups' LDS.128 land on disjoint banks (1 wf, was 4).
#define PD_F 272
#define PSLOT(s) ((s) + 4 * ((s) >> 6))

// ---------------------------------------------------------------------------
// Device scratch
// ---------------------------------------------------------------------------
__device__ float g_expA[QS * QS];     // exp(log_A)  [j][i]
__device__ float g_expAT[QS * QS];    // transpose
__device__ float g_expB[QS * 32];
__device__ float g_pi[QS];
__device__ float g_emit[NPOST];       // [b][l][q]
__device__ float g_alpha[NPOST];
__device__ float g_beta[NPOST];
__device__ float g_Ca[NB * LS];
__device__ float g_Cb[NB * LS];
__device__ float g_loglik[NB];

// ---------------------------------------------------------------------------
// f32x2 helpers
// ---------------------------------------------------------------------------
__device__ __forceinline__ unsigned long long pk(float x, float y) {
    unsigned long long r;
    asm("mov.b64 %0, {%1,%2};" : "=l"(r) : "f"(x), "f"(y));
    return r;
}
__device__ __forceinline__ void ffma2(unsigned long long& c,
                                      unsigned long long a,
                                      unsigned long long b) {
    asm("fma.rn.f32x2 %0, %1, %2, %0;" : "+l"(c) : "l"(a), "l"(b));
}
__device__ __forceinline__ unsigned long long mul2(unsigned long long a,
                                                   unsigned long long b) {
    unsigned long long r;
    asm("mul.rn.f32x2 %0, %1, %2;" : "=l"(r) : "l"(a), "l"(b));
    return r;
}
__device__ __forceinline__ unsigned long long add2(unsigned long long a,
                                                   unsigned long long b) {
    unsigned long long r;
    asm("add.rn.f32x2 %0, %1, %2;" : "=l"(r) : "l"(a), "l"(b));
    return r;
}
__device__ __forceinline__ float2 unpk(unsigned long long u) {
    float lo, hi;
    asm("mov.b64 {%0,%1}, %2;" : "=f"(lo), "=f"(hi) : "l"(u));
    return make_float2(lo, hi);
}
__device__ __forceinline__ unsigned long long shfl_xor_u64(unsigned long long v, int m) {
    float2 f = unpk(v);
    f.x = __shfl_xor_sync(0xffffffffu, f.x, m);
    f.y = __shfl_xor_sync(0xffffffffu, f.y, m);
    return pk(f.x, f.y);
}

// ---------------------------------------------------------------------------
// Kernel 0: exp() of parameters
// ---------------------------------------------------------------------------
__global__ void precompute_kernel(const float* __restrict__ log_A,
                                  const float* __restrict__ log_pi,
                                  const float* __restrict__ log_B) {
    int idx = blockIdx.x * 256 + threadIdx.x;
    if (blockIdx.x < 256) {
        float v = expf(log_A[idx]);
        g_expA[idx] = v;
        int j = idx >> 8, i = idx & 255;
        g_expAT[i * QS + j] = v;
    } else if (blockIdx.x < 282) {
        int k = idx - 65536;
        if (k < QS * SS) {
            int q = k / SS, s = k - q * SS;
            g_expB[q * 32 + s] = expf(log_B[k]);
        }
    } else {
        if (threadIdx.x < QS) g_pi[threadIdx.x] = expf(log_pi[threadIdx.x]);
    }
}

// ---------------------------------------------------------------------------
// Kernel 1: emission GEMM
// ---------------------------------------------------------------------------
__global__ void __launch_bounds__(256) emission_kernel(const float* __restrict__ inputs) {
    __shared__ float in_sh[EM_ROWS][SS];
    int tid = threadIdx.x;
    int row0 = blockIdx.x * EM_ROWS;

    for (int i = tid; i < EM_ROWS * SS; i += 256)
        in_sh[i / SS][i % SS] = inputs[row0 * SS + i];
    float eb[SS];
#pragma unroll
    for (int s = 0; s < SS; s++) eb[s] = g_expB[tid * 32 + s];
    __syncthreads();

#pragma unroll 4
    for (int r = 0; r < EM_ROWS; r++) {
        float acc = 0.0f;
#pragma unroll
        for (int s = 0; s < SS; s++) acc = fmaf(in_sh[r][s], eb[s], acc);
        g_emit[(size_t)(row0 + r) * QS + tid] = acc;
    }
}

// ---------------------------------------------------------------------------
// ncu alignment marker (no work; shifts fb to the profiled launch slot)
// ---------------------------------------------------------------------------
__global__ void fb_marker_kernel() {}

// ---------------------------------------------------------------------------
// Kernel 2: scaled forward/backward, deferred renormalization, pure fp32.
// Block 0..63 forward chain b; block 64..127 backward chain b-64.
// ---------------------------------------------------------------------------
extern __shared__ unsigned int shu[];

#define SH_MYROW  (shu)
#define SH_P(bf)  ((float*)(shu + MYROW_U32) + (bf) * PD_F)
#define SH_RED    ((float*)(shu + MYROW_U32) + 2 * PD_F)

__global__ void __launch_bounds__(256, 1) fb_kernel() {
    int tid  = threadIdx.x;
    int w    = tid >> 5;
    int lane = tid & 31;
    int g    = lane >> 3;
    int li   = lane & 7;
    int cc   = 32 * w + 4 * li;          // my 4 columns
    int r0   = 64 * g;                   // my 64 rows

    int bx = blockIdx.x;
    bool fwd = (bx < NB);
    int b = fwd ? bx : bx - NB;
    const float* Ag = fwd ? g_expA : g_expAT;

    // rows r0..r0+39 -> fp32 row-pair regs: Areg[j2*4+c] = (A[r0+2j2][cc+c], A[r0+2j2+1][cc+c])
    unsigned long long Areg[80];
#pragma unroll
    for (int j2 = 0; j2 < 20; j2++) {
        const float* ra = Ag + (r0 + 2 * j2) * QS + cc;
        const float* rb = ra + QS;
#pragma unroll
        for (int c = 0; c < 4; c++)
            Areg[j2 * 4 + c] = pk(ra[c], rb[c]);
    }
    // rows r0+40..r0+63 -> fp32 row-pairs in private shared row
    unsigned long long* myrow64 =
        (unsigned long long*)(SH_MYROW + tid * MYROW_PITCH);
#pragma unroll
    for (int j2 = 0; j2 < 12; j2++) {
        const float* ra = Ag + (r0 + 40 + 2 * j2) * QS + cc;
        const float* rb = ra + QS;
#pragma unroll
        for (int c = 0; c < 4; c++)
            myrow64[j2 * 4 + c] = pk(ra[c], rb[c]);
    }

    const float* em_b = g_emit + (size_t)b * LS * QS;
    float* st_b = (fwd ? g_alpha : g_beta) + (size_t)b * LS * QS;
    float* C_b  = (fwd ? g_Ca : g_Cb) + b * LS;

    // --- boundary init (skewed p slots) ---
    {
        int s = tid;
        if (fwd) {
            float v = g_pi[s] * em_b[s];
            st_b[s] = v;
            SH_P(0)[PSLOT(s)] = v;
            if (s == 0) C_b[0] = 0.0f;
        } else {
            st_b[(size_t)(LS - 1) * QS + s] = 1.0f;
            SH_P(0)[PSLOT(s)] = em_b[(size_t)(LS - 1) * QS + s];
            if (s == 0) C_b[LS - 1] = 0.0f;
        }
    }
    __syncthreads();

    double C = 0.0;
    int cur = 0;
    int t    = fwd ? 1 : (LS - 2);
    int tend = fwd ? LS : -1;
    int tinc = fwd ? 1 : -1;
    const unsigned FULL = 0xffffffffu;
    int pd_base = 68 * g;                 // skewed chunk base for my row-group
    int pslot_w = PSLOT(cc);              // skewed write slot for my columns

    for (; t != tend; t += tinc) {
        float4 e4 = *(const float4*)(em_b + (size_t)t * QS + cc);

        // ---- matvec: my 64 rows x 4 cols ----
        const ulonglong2* pdv = (const ulonglong2*)(SH_P(cur) + pd_base);
        unsigned long long acc[4];
        {
            ulonglong2 q = pdv[0];                 // (p[r0],p[r0+1]) , (p[r0+2],p[r0+3])
            acc[0] = mul2(Areg[0], q.x);
            acc[1] = mul2(Areg[1], q.x);
            acc[2] = mul2(Areg[2], q.x);
            acc[3] = mul2(Areg[3], q.x);
            ffma2(acc[0], Areg[4], q.y);
            ffma2(acc[1], Areg[5], q.y);
            ffma2(acc[2], Areg[6], q.y);
            ffma2(acc[3], Areg[7], q.y);
        }
#pragma unroll
        for (int k = 1; k < 10; k++) {
            ulonglong2 q = pdv[k];
#pragma unroll
            for (int c = 0; c < 4; c++) ffma2(acc[c], Areg[8 * k + c], q.x);
#pragma unroll
            for (int c = 0; c < 4; c++) ffma2(acc[c], Areg[8 * k + 4 + c], q.y);
        }
        // shared fp32 rows: pairs (2k, 2k+1), 4 LDS.128 per k
#pragma unroll
        for (int k = 0; k < 6; k++) {
            ulonglong2 q = pdv[10 + k];
            const ulonglong2* mrow = (const ulonglong2*)(myrow64 + 8 * k);
            ulonglong2 wa0 = mrow[0];   // pair 2k,   cols 0,1
            ulonglong2 wa1 = mrow[1];   // pair 2k,   cols 2,3
            ulonglong2 wb0 = mrow[2];   // pair 2k+1, cols 0,1
            ulonglong2 wb1 = mrow[3];   // pair 2k+1, cols 2,3
            ffma2(acc[0], wa0.x, q.x);
            ffma2(acc[1], wa0.y, q.x);
            ffma2(acc[2], wa1.x, q.x);
            ffma2(acc[3], wa1.y, q.x);
            ffma2(acc[0], wb0.x, q.y);
            ffma2(acc[1], wb0.y, q.y);
            ffma2(acc[2], wb1.x, q.y);
            ffma2(acc[3], wb1.y, q.y);
        }

        // ---- reduce across the 4 row-groups (symmetric butterfly) ----
#pragma unroll
        for (int c = 0; c < 4; c++) acc[c] = add2(acc[c], shfl_xor_u64(acc[c], 8));
#pragma unroll
        for (int c = 0; c < 4; c++) acc[c] = add2(acc[c], shfl_xor_u64(acc[c], 16));

        float2 s0 = unpk(acc[0]), s1 = unpk(acc[1]), s2 = unpk(acc[2]), s3 = unpk(acc[3]);
        float m0 = s0.x + s0.y, m1 = s1.x + s1.y, m2 = s2.x + s2.y, m3 = s3.x + s3.y;

        float Ct = (float)C;
        bool renorm = fwd ? ((t & 15) == 15) : ((t & 15) == 0);
        float4 stv;
        float4 pv;

        if (fwd) {
            stv = make_float4(m0 * e4.x, m1 * e4.y, m2 * e4.z, m3 * e4.w);
            pv = stv;
            if (renorm) {
                float ls = (stv.x + stv.y) + (stv.z + stv.w);
                ls += __shfl_xor_sync(FULL, ls, 1);
                ls += __shfl_xor_sync(FULL, ls, 2);
                ls += __shfl_xor_sync(FULL, ls, 4);
                if (lane == 0) SH_RED[w] = ls;
                __syncthreads();
                float s = 0.0f;
#pragma unroll
                for (int ww = 0; ww < 8; ww++) s += SH_RED[ww];
                if (t == LS - 1 && tid == 0)
                    g_loglik[b] = (float)(C + (double)logf(s));
                C += (double)logf(s);
                float inv = 1.0f / s;
                pv = make_float4(stv.x * inv, stv.y * inv, stv.z * inv, stv.w * inv);
            }
        } else {
            stv = make_float4(m0, m1, m2, m3);
            float4 q = stv;
            if (renorm) {
                float ls = (m0 + m1) + (m2 + m3);
                ls += __shfl_xor_sync(FULL, ls, 1);
                ls += __shfl_xor_sync(FULL, ls, 2);
                ls += __shfl_xor_sync(FULL, ls, 4);
                if (lane == 0) SH_RED[w] = ls;
                __syncthreads();
                float s = 0.0f;
#pragma unroll
                for (int ww = 0; ww < 8; ww++) s += SH_RED[ww];
                C += (double)logf(s);
                float inv = 1.0f / s;
                q = make_float4(m0 * inv, m1 * inv, m2 * inv, m3 * inv);
            }
            pv = make_float4(q.x * e4.x, q.y * e4.y, q.z * e4.z, q.w * e4.w);
        }

        if (g == 0)
            *(float4*)(SH_P(cur ^ 1) + pslot_w) = pv;
        __syncthreads();
        if (g == 0)
            *(float4*)(st_b + (size_t)t * QS + cc) = stv;   // overlaps next matvec
        if (tid == 0) C_b[t] = Ct;
        cur ^= 1;
    }
}

// ---------------------------------------------------------------------------
// Kernel 3: posterior + loglik
// ---------------------------------------------------------------------------
__global__ void __launch_bounds__(256) posterior_kernel(float* __restrict__ out, int out_size) {
    int i4 = blockIdx.x * 256 + threadIdx.x;
    int idx = i4 << 2;
    int bt = idx >> 8;
    int b  = bt >> 11;
    float4 a  = *(const float4*)(g_alpha + idx);
    float4 be = *(const float4*)(g_beta + idx);
    float c = g_Ca[bt] + g_Cb[bt] - g_loglik[b];
    float4 o;
    o.x = logf(a.x * be.x) + c;
    o.y = logf(a.y * be.y) + c;
    o.z = logf(a.z * be.z) + c;
    o.w = logf(a.w * be.w) + c;
    *(float4*)(out + idx) = o;
    if (i4 < NB && out_size >= NPOST + NB)
        out[NPOST + i4] = g_loglik[i4];
}

// ---------------------------------------------------------------------------
// Launch
// ---------------------------------------------------------------------------
extern "C" void kernel_launch(void* const* d_in, const int* in_sizes, int n_in,
                              void* d_out, int out_size) {
    const float* inputs = (const float*)d_in[0];   // (1,64,2048,26)
    const float* log_A  = (const float*)d_in[1];   // (1,256,256)
    const float* log_pi = (const float*)d_in[2];   // (1,256)
    const float* log_B  = (const float*)d_in[3];   // (1,256,26)
    float* out = (float*)d_out;

    precompute_kernel<<<283, 256>>>(log_A, log_pi, log_B);
    emission_kernel<<<(NB * LS) / EM_ROWS, 256>>>(inputs);
    fb_marker_kernel<<<1, 32>>>();                 // keeps fb in ncu's -s 5 slot

    int smem = (MYROW_U32 + 2 * PD_F + 16 + 16) * (int)sizeof(unsigned int);
    cudaFuncSetAttribute(fb_kernel, cudaFuncAttributeMaxDynamicSharedMemorySize, smem);
    fb_kernel<<<2 * NB, 256, smem>>>();

    posterior_kernel<<<NPOST / 1024, 256>>>(out, out_size);
}